// round 15
// baseline (speedup 1.0000x reference)
#include <cuda_runtime.h>
#include <cuda_fp16.h>
#include <cstdint>

// Problem constants
#define NN      8192
#define IN_DIM  256
#define HID     192
#define OUT_DIM 3
#define LBLK    6

// SIMT projection GEMM tiling (BM=32 for 2-CTA/SM co-residency)
#define BM 32
#define BN 192
#define BK 16
#define TM 2
#define TN 12

// ---------------------------------------------------------------------------
// Scratch (device globals — no allocation allowed)
// ---------------------------------------------------------------------------
__device__ float g_h [NN * HID];
__device__ float g_t [NN * HID];
__device__ float g_U [NN * HID];
__device__ float g_Y3[NN * OUT_DIM];
__device__ float g_U3[NN * OUT_DIM];
__device__ __half g_adj_hi[(size_t)NN * NN];   // 128 MB (fp16 hi)
__device__ __half g_adj_lo[(size_t)NN * NN];   // 128 MB (fp16 residual)
__device__ __half g_yt_hi[HID * NN];           // Y^T fp16 (k-contiguous)

// ---------------------------------------------------------------------------
// helpers
// ---------------------------------------------------------------------------
__device__ __forceinline__ uint32_t smem_u32(const void* p) {
    uint32_t a;
    asm("{ .reg .u64 t; cvta.to.shared.u64 t, %1; cvt.u32.u64 %0, t; }"
        : "=r"(a) : "l"(p));
    return a;
}
#define SWZ(o) ((o) ^ (((o) >> 3) & 0x70))

__device__ __forceinline__ void cp_async16(uint32_t dst, const void* src) {
    asm volatile("cp.async.cg.shared.global [%0], [%1], 16;"
                 :: "r"(dst), "l"(src) : "memory");
}
__device__ __forceinline__ void cp_commit() {
    asm volatile("cp.async.commit_group;" ::: "memory");
}
template <int N>
__device__ __forceinline__ void cp_wait() {
    asm volatile("cp.async.wait_group %0;" :: "n"(N) : "memory");
}
__device__ __forceinline__ void ldmx4(uint32_t* r, uint32_t addr) {
    asm volatile("ldmatrix.sync.aligned.m8n8.x4.shared.b16 {%0,%1,%2,%3}, [%4];"
                 : "=r"(r[0]), "=r"(r[1]), "=r"(r[2]), "=r"(r[3]) : "r"(addr));
}
__device__ __forceinline__ void mma16816(float* c, const uint32_t* a,
                                         uint32_t b0, uint32_t b1) {
    asm volatile(
        "mma.sync.aligned.m16n8k16.row.col.f32.f16.f16.f32 "
        "{%0,%1,%2,%3}, {%4,%5,%6,%7}, {%8,%9}, {%0,%1,%2,%3};"
        : "+f"(c[0]), "+f"(c[1]), "+f"(c[2]), "+f"(c[3])
        : "r"(a[0]), "r"(a[1]), "r"(a[2]), "r"(a[3]), "r"(b0), "r"(b1));
}

// ---------------------------------------------------------------------------
// adj fp32 -> fp16 hi/lo split
// ---------------------------------------------------------------------------
__global__ __launch_bounds__(256) void convert_adj(const float* __restrict__ adj)
{
    size_t i = (size_t)blockIdx.x * 256 + threadIdx.x;   // float4 index
    float4 v = ((const float4*)adj)[i];
    __half h0 = __float2half_rn(v.x);
    __half h1 = __float2half_rn(v.y);
    __half h2 = __float2half_rn(v.z);
    __half h3 = __float2half_rn(v.w);
    __half l0 = __float2half_rn(v.x - __half2float(h0));
    __half l1 = __float2half_rn(v.y - __half2float(h1));
    __half l2 = __float2half_rn(v.z - __half2float(h2));
    __half l3 = __float2half_rn(v.w - __half2float(h3));
    uint32_t hw0 = (uint32_t)(*(unsigned short*)&h0) | ((uint32_t)(*(unsigned short*)&h1) << 16);
    uint32_t hw1 = (uint32_t)(*(unsigned short*)&h2) | ((uint32_t)(*(unsigned short*)&h3) << 16);
    uint32_t lw0 = (uint32_t)(*(unsigned short*)&l0) | ((uint32_t)(*(unsigned short*)&l1) << 16);
    uint32_t lw1 = (uint32_t)(*(unsigned short*)&l2) | ((uint32_t)(*(unsigned short*)&l3) << 16);
    ((uint2*)g_adj_hi)[i] = make_uint2(hw0, hw1);
    ((uint2*)g_adj_lo)[i] = make_uint2(lw0, lw1);
}

// ---------------------------------------------------------------------------
// HMMA adj GEMM with intra-CTA split-K, fp16 2-pass:
//   out = epilogue( (Ahi + Alo) @ fp16(Y) )
//   mode 1: out = relu(acc + U);  mode 2: out = (R + relu(acc + U)) * 0.5
// grid 128: bx>>1 -> 128-row strip, bx&1 -> 96-col half.
// 512 threads = 16 warps = 2 k-halves x 8 warps; warp tile 32x48.
// Epilogue split across halves.
// ---------------------------------------------------------------------------
#define A_HI_OFF 0
#define A_LO_OFF 16384
#define B_HI_OFF 32768
#define ST_BYTES 45056
#define MMA_SMEM (4 * ST_BYTES)   // 180224

__global__ __launch_bounds__(512, 1) void adj_mma(
    const __half* __restrict__ Ahi, const __half* __restrict__ Alo,
    const __half* __restrict__ Bhi,
    const float* __restrict__ U, const float* __restrict__ R,
    float* __restrict__ out, int mode)
{
    extern __shared__ __align__(1024) char smem[];
    const uint32_t sb = smem_u32(smem);
    const int tid  = threadIdx.x;
    const int warp = tid >> 5;
    const int lane = tid & 31;
    const int half = warp >> 3;        // k-half 0/1
    const int wid8 = warp & 7;
    const int ltid = tid & 255;
    const int m0   = (blockIdx.x >> 1) * 128;
    const int n0   = (blockIdx.x & 1) * 96;
    const int wm   = wid8 & 3;
    const int wn   = wid8 >> 2;
    const uint32_t hb = sb + (uint32_t)half * 2 * ST_BYTES;

    float acc[2][6][4];
#pragma unroll
    for (int mt = 0; mt < 2; mt++)
#pragma unroll
        for (int nt = 0; nt < 6; nt++)
#pragma unroll
            for (int q = 0; q < 4; q++) acc[mt][nt][q] = 0.f;

    // ldmatrix per-lane offsets
    int a_off[2], xa[2];
#pragma unroll
    for (int mt = 0; mt < 2; mt++) {
        int r = wm * 32 + mt * 16 + (lane & 15);
        a_off[mt] = r * 128 + (lane >> 4) * 16;
        xa[mt] = (a_off[mt] >> 3) & 0x70;
    }
    int b_off[3], xb[3];
#pragma unroll
    for (int p = 0; p < 3; p++) {
        int r = wn * 48 + p * 16 + (lane & 7) + ((lane >> 4) << 3);
        b_off[p] = r * 128 + ((lane >> 3) & 1) * 16;
        xb[p] = (b_off[p] >> 3) & 0x70;
    }

    auto issue = [&](int lc) {
        const uint32_t stage = hb + (uint32_t)(lc & 1) * ST_BYTES;
        const int k0 = (half * 64 + lc) << 6;
#pragma unroll
        for (int p = 0; p < 4; p++) {
            int f = p * 256 + ltid, r = f >> 3, j = f & 7;
            size_t src = (size_t)(m0 + r) * NN + k0 + j * 8;
            uint32_t d = SWZ((uint32_t)(r * 128 + j * 16));
            cp_async16(stage + A_HI_OFF + d, Ahi + src);
            cp_async16(stage + A_LO_OFF + d, Alo + src);
        }
#pragma unroll
        for (int p = 0; p < 3; p++) {
            int f = p * 256 + ltid, r = f >> 3, j = f & 7;
            size_t src = (size_t)(n0 + r) * NN + k0 + j * 8;
            uint32_t d = SWZ((uint32_t)(r * 128 + j * 16));
            cp_async16(stage + B_HI_OFF + d, Bhi + src);
        }
        cp_commit();
    };

    auto hbar = [&]() {
        asm volatile("bar.sync %0, %1;" :: "r"(half + 1), "r"(256) : "memory");
    };

    const int NCH = 64;   // chunks per half
    issue(0);
    issue(1);
    for (int lc = 0; lc < NCH; lc++) {
        if (lc + 1 < NCH) cp_wait<1>(); else cp_wait<0>();
        hbar();
        const uint32_t base = hb + (uint32_t)(lc & 1) * ST_BYTES;
#pragma unroll
        for (int ks = 0; ks < 4; ks++) {
            const int kb = ks * 32;
            uint32_t ah[2][4], al[2][4], bh[3][4];
#pragma unroll
            for (int mt = 0; mt < 2; mt++) {
                uint32_t d = (uint32_t)((a_off[mt] + kb) ^ xa[mt]);
                ldmx4(ah[mt], base + A_HI_OFF + d);
                ldmx4(al[mt], base + A_LO_OFF + d);
            }
#pragma unroll
            for (int p = 0; p < 3; p++) {
                uint32_t d = (uint32_t)((b_off[p] + kb) ^ xb[p]);
                ldmx4(bh[p], base + B_HI_OFF + d);
            }
#pragma unroll
            for (int mt = 0; mt < 2; mt++)
#pragma unroll
                for (int nt = 0; nt < 6; nt++) {
                    const int q = nt >> 1, o = (nt & 1) * 2;
                    mma16816(acc[mt][nt], ah[mt], bh[q][o], bh[q][o + 1]);
                }
#pragma unroll
            for (int mt = 0; mt < 2; mt++)
#pragma unroll
                for (int nt = 0; nt < 6; nt++) {
                    const int q = nt >> 1, o = (nt & 1) * 2;
                    mma16816(acc[mt][nt], al[mt], bh[q][o], bh[q][o + 1]);
                }
        }
        hbar();   // all 8 warps of this half done reading stage (lc&1)
        if (lc + 2 < NCH) issue(lc + 2);
    }

    // cross-half exchange: half0 stores nt3..5, half1 stores nt0..2.
    __syncthreads();
    float* red = (float*)smem;   // 256 lanes x 48 floats = 49152 B
    float* pr = red + (wid8 * 32 + lane) * 48;
    if (half == 0) {
#pragma unroll
        for (int mt = 0; mt < 2; mt++)
#pragma unroll
            for (int nt = 3; nt < 6; nt++)
#pragma unroll
                for (int q = 0; q < 4; q++)
                    pr[24 + mt * 12 + (nt - 3) * 4 + q] = acc[mt][nt][q];
    } else {
#pragma unroll
        for (int mt = 0; mt < 2; mt++)
#pragma unroll
            for (int nt = 0; nt < 3; nt++)
#pragma unroll
                for (int q = 0; q < 4; q++)
                    pr[mt * 12 + nt * 4 + q] = acc[mt][nt][q];
    }
    __syncthreads();

    const int tr = lane >> 2;
    const int tc = (lane & 3) * 2;
    const int ntb = half * 3;   // half0 -> nt 0..2, half1 -> nt 3..5
#pragma unroll
    for (int mt = 0; mt < 2; mt++)
#pragma unroll
        for (int k3 = 0; k3 < 3; k3++) {
            const int nt = ntb + k3;
            const int po = (half == 0) ? (mt * 12 + nt * 4) : (24 + mt * 12 + k3 * 4);
#pragma unroll
            for (int hh = 0; hh < 2; hh++) {
                const int row = m0 + wm * 32 + mt * 16 + tr + hh * 8;
                const int col = n0 + wn * 48 + nt * 8 + tc;
                const size_t idx = (size_t)row * HID + col;
                float v0 = acc[mt][nt][hh * 2 + 0] + pr[po + hh * 2 + 0];
                float v1 = acc[mt][nt][hh * 2 + 1] + pr[po + hh * 2 + 1];
                const float2 u = *(const float2*)(U + idx);
                v0 = fmaxf(v0 + u.x, 0.f);
                v1 = fmaxf(v1 + u.y, 0.f);
                if (mode == 2) {
                    const float2 rr = *(const float2*)(R + idx);
                    v0 = (rr.x + v0) * 0.5f;
                    v1 = (rr.y + v1) * 0.5f;
                }
                *(float2*)(out + idx) = make_float2(v0, v1);
            }
        }
}

// ---------------------------------------------------------------------------
// Fused projection (BM=32, grid 256 -> ~2 CTAs/SM co-residency):
//   Y = A@W (-> transposed fp16, smem-staged coalesced), U = A@Wl + bias
// ---------------------------------------------------------------------------
#define YT_STRIDE 40
#define PROJ_SMEM ((2 * BK * (BM + 4) + 2 * 2 * BK * BN) * 4)   // 53760

__global__ __launch_bounds__(256) void proj_fused(
    const float* __restrict__ A, int K,
    const float* __restrict__ W,
    const float* __restrict__ Wl,
    const float* __restrict__ bias,
    __half* __restrict__ yth,
    float* __restrict__ Uo)
{
    extern __shared__ __align__(16) float ps[];
    float* As  = ps;                              // [2][BK][BM+4]
    float* BsY = ps + 2 * BK * (BM + 4);          // [2][BK][BN]
    float* BsU = BsY + 2 * BK * BN;               // [2][BK][BN]

    const int tid = threadIdx.x;
    const int m0  = blockIdx.x * BM;

    // A tile: 32 rows x 16 k = 128 float4s; threads 0..127 load one each
    const int am = (tid & 127) >> 2;
    const int ak = (tid & 3) * 4;
    const float* Aptr = A + (size_t)(m0 + am) * (size_t)K + ak;

    const int tx = tid & 15;   // col group (12 cols)
    const int ty = tid >> 4;   // row group (2 rows)

    float accY[TM][TN], accU[TM][TN];
#pragma unroll
    for (int i = 0; i < TM; i++)
#pragma unroll
        for (int j = 0; j < TN; j++) { accY[i][j] = 0.f; accU[i][j] = 0.f; }

    const int nk = K / BK;

    auto loadA = [&](int buf, int k0) {
        if (tid < 128) {
            float4 v = *(const float4*)(Aptr + k0);
            float* dst = As + buf * BK * (BM + 4);
            dst[(ak + 0) * (BM + 4) + am] = v.x;
            dst[(ak + 1) * (BM + 4) + am] = v.y;
            dst[(ak + 2) * (BM + 4) + am] = v.z;
            dst[(ak + 3) * (BM + 4) + am] = v.w;
        }
    };
    auto loadB = [&](int buf, int k0) {
#pragma unroll
        for (int i = 0; i < 3; i++) {
            int f  = i * 256 + tid;
            int kr = f / 48;
            int c4 = f % 48;
            size_t src = (size_t)(k0 + kr) * BN + c4 * 4;
            *(float4*)(BsY + buf * BK * BN + kr * BN + c4 * 4) = *(const float4*)(W  + src);
            *(float4*)(BsU + buf * BK * BN + kr * BN + c4 * 4) = *(const float4*)(Wl + src);
        }
    };

    loadA(0, 0);
    loadB(0, 0);
    __syncthreads();

    int buf = 0;
    for (int kb = 0; kb < nk; kb++) {
        if (kb + 1 < nk) {
            int k0n = (kb + 1) * BK;
            loadA(buf ^ 1, k0n);
            loadB(buf ^ 1, k0n);
        }
        const float* Ab = As + buf * BK * (BM + 4);
        const float* BY = BsY + buf * BK * BN;
        const float* BU = BsU + buf * BK * BN;
#pragma unroll
        for (int k = 0; k < BK; k++) {
            float a[TM];
            float2 av = *(const float2*)(Ab + k * (BM + 4) + ty * 2);
            a[0] = av.x; a[1] = av.y;
            float by[TN], bu[TN];
#pragma unroll
            for (int q = 0; q < 3; q++) {
                float4 v = *(const float4*)(BY + k * BN + tx * 12 + q * 4);
                by[q * 4 + 0] = v.x; by[q * 4 + 1] = v.y;
                by[q * 4 + 2] = v.z; by[q * 4 + 3] = v.w;
                float4 u = *(const float4*)(BU + k * BN + tx * 12 + q * 4);
                bu[q * 4 + 0] = u.x; bu[q * 4 + 1] = u.y;
                bu[q * 4 + 2] = u.z; bu[q * 4 + 3] = u.w;
            }
#pragma unroll
            for (int i = 0; i < TM; i++)
#pragma unroll
                for (int j = 0; j < TN; j++) {
                    accY[i][j] += a[i] * by[j];
                    accU[i][j] += a[i] * bu[j];
                }
        }
        __syncthreads();
        buf ^= 1;
    }

    float bv[TN];
#pragma unroll
    for (int j = 0; j < TN; j++) bv[j] = bias[tx * 12 + j];

    // U output (fp32, coalesced row-major)
#pragma unroll
    for (int i = 0; i < TM; i++) {
        const int row = m0 + ty * 2 + i;
        const size_t base = (size_t)row * BN + tx * 12;
        float4* o = (float4*)(Uo + base);
        o[0] = make_float4(accU[i][0] + bv[0], accU[i][1] + bv[1], accU[i][2]  + bv[2],  accU[i][3]  + bv[3]);
        o[1] = make_float4(accU[i][4] + bv[4], accU[i][5] + bv[5], accU[i][6]  + bv[6],  accU[i][7]  + bv[7]);
        o[2] = make_float4(accU[i][8] + bv[8], accU[i][9] + bv[9], accU[i][10] + bv[10], accU[i][11] + bv[11]);
    }

    // Y output: stage transposed fp16 in smem, then coalesced flush
    __syncthreads();   // main-loop smem dead; reuse
    __half* sh = (__half*)ps;                 // [BN][YT_STRIDE]
#pragma unroll
    for (int i = 0; i < TM; i++) {
        const int r = ty * 2 + i;     // local row 0..31
#pragma unroll
        for (int j = 0; j < TN; j++) {
            const int col = tx * 12 + j;
            sh[col * YT_STRIDE + r] = __float2half_rn(accY[i][j]);
        }
    }
    __syncthreads();
    // flush: 192 cols x 32 rows, 2 fp16 per thread-step
    for (int idx = tid; idx < BN * (BM / 2); idx += 256) {
        const int col = idx >> 4;
        const int r2  = (idx & 15) * 2;
        uint32_t vh = (uint32_t)*(const unsigned short*)&sh[col * YT_STRIDE + r2]
                    | ((uint32_t)*(const unsigned short*)&sh[col * YT_STRIDE + r2 + 1] << 16);
        *(uint32_t*)(yth + (size_t)col * NN + m0 + r2) = vh;
    }
}

// ---------------------------------------------------------------------------
// Output head
// ---------------------------------------------------------------------------
__global__ __launch_bounds__(256) void out_proj(
    const float* __restrict__ h,
    const float* __restrict__ W,
    const float* __restrict__ Wl,
    const float* __restrict__ b,
    float* __restrict__ Y3,
    float* __restrict__ U3)
{
    __shared__ float sW[HID * OUT_DIM];
    __shared__ float sWl[HID * OUT_DIM];
    for (int i = threadIdx.x; i < HID * OUT_DIM; i += blockDim.x) {
        sW[i]  = W[i];
        sWl[i] = Wl[i];
    }
    __syncthreads();

    int m = blockIdx.x * blockDim.x + threadIdx.x;
    if (m >= NN) return;

    const float* hr = h + (size_t)m * HID;
    float a0 = 0.f, a1 = 0.f, a2 = 0.f;
    float l0 = 0.f, l1 = 0.f, l2 = 0.f;
#pragma unroll 4
    for (int k = 0; k < HID; k++) {
        float hv = hr[k];
        a0 += hv * sW[k * 3 + 0];
        a1 += hv * sW[k * 3 + 1];
        a2 += hv * sW[k * 3 + 2];
        l0 += hv * sWl[k * 3 + 0];
        l1 += hv * sWl[k * 3 + 1];
        l2 += hv * sWl[k * 3 + 2];
    }
    Y3[m * 3 + 0] = a0; Y3[m * 3 + 1] = a1; Y3[m * 3 + 2] = a2;
    U3[m * 3 + 0] = l0 + b[0];
    U3[m * 3 + 1] = l1 + b[1];
    U3[m * 3 + 2] = l2 + b[2];
}

__global__ __launch_bounds__(256) void adj_small(
    const float* __restrict__ adj,
    const float* __restrict__ Y3,
    const float* __restrict__ U3,
    float* __restrict__ out)
{
    const int lane   = threadIdx.x & 31;
    const int warp   = (blockIdx.x * blockDim.x + threadIdx.x) >> 5;
    const int nwarps = (gridDim.x * blockDim.x) >> 5;

    for (int m = warp; m < NN; m += nwarps) {
        const float4* ar = (const float4*)(adj + (size_t)m * NN);
        float a0 = 0.f, a1 = 0.f, a2 = 0.f;
        for (int f = lane; f < NN / 4; f += 32) {
            float4 v = ar[f];
            int k = f * 4;
            a0 += v.x * Y3[(k + 0) * 3 + 0] + v.y * Y3[(k + 1) * 3 + 0]
                + v.z * Y3[(k + 2) * 3 + 0] + v.w * Y3[(k + 3) * 3 + 0];
            a1 += v.x * Y3[(k + 0) * 3 + 1] + v.y * Y3[(k + 1) * 3 + 1]
                + v.z * Y3[(k + 2) * 3 + 1] + v.w * Y3[(k + 3) * 3 + 1];
            a2 += v.x * Y3[(k + 0) * 3 + 2] + v.y * Y3[(k + 1) * 3 + 2]
                + v.z * Y3[(k + 2) * 3 + 2] + v.w * Y3[(k + 3) * 3 + 2];
        }
#pragma unroll
        for (int off = 16; off > 0; off >>= 1) {
            a0 += __shfl_down_sync(0xffffffffu, a0, off);
            a1 += __shfl_down_sync(0xffffffffu, a1, off);
            a2 += __shfl_down_sync(0xffffffffu, a2, off);
        }
        if (lane == 0) {
            out[m * 3 + 0] = a0 + U3[m * 3 + 0];
            out[m * 3 + 1] = a1 + U3[m * 3 + 1];
            out[m * 3 + 2] = a2 + U3[m * 3 + 2];
        }
    }
}

// ---------------------------------------------------------------------------
extern "C" void kernel_launch(void* const* d_in, const int* in_sizes, int n_in,
                              void* d_out, int out_size)
{
    const float* x      = (const float*)d_in[0];
    const float* adj    = (const float*)d_in[1];
    const float* in_W   = (const float*)d_in[2];
    const float* in_Wl  = (const float*)d_in[3];
    const float* in_b   = (const float*)d_in[4];
    const float* blk_W1  = (const float*)d_in[5];
    const float* blk_Wl1 = (const float*)d_in[6];
    const float* blk_b1  = (const float*)d_in[7];
    const float* blk_W2  = (const float*)d_in[8];
    const float* blk_Wl2 = (const float*)d_in[9];
    const float* blk_b2  = (const float*)d_in[10];
    const float* out_W  = (const float*)d_in[11];
    const float* out_Wl = (const float*)d_in[12];
    const float* out_b  = (const float*)d_in[13];
    float* out = (float*)d_out;

    float *h, *t, *U, *Y3, *U3;
    __half *ahi, *alo, *yth;
    cudaGetSymbolAddress((void**)&h,   g_h);
    cudaGetSymbolAddress((void**)&t,   g_t);
    cudaGetSymbolAddress((void**)&U,   g_U);
    cudaGetSymbolAddress((void**)&Y3,  g_Y3);
    cudaGetSymbolAddress((void**)&U3,  g_U3);
    cudaGetSymbolAddress((void**)&ahi, g_adj_hi);
    cudaGetSymbolAddress((void**)&alo, g_adj_lo);
    cudaGetSymbolAddress((void**)&yth, g_yt_hi);

    cudaFuncSetAttribute(adj_mma,    cudaFuncAttributeMaxDynamicSharedMemorySize, MMA_SMEM);
    cudaFuncSetAttribute(proj_fused, cudaFuncAttributeMaxDynamicSharedMemorySize, PROJ_SMEM);

    const dim3 blk(256);
    const dim3 blk512(512);
    const dim3 gproj(NN / BM);   // 256
    const dim3 gmma(128);

    // split adj into fp16 hi/lo
    convert_adj<<<NN * (NN / 4) / 256, blk>>>(adj);

    // input gconv: h = relu(adj @ (x@in_W) + x@in_Wl + in_b)
    proj_fused<<<gproj, blk, PROJ_SMEM>>>(x, IN_DIM, in_W, in_Wl, in_b, yth, U);
    adj_mma<<<gmma, blk512, MMA_SMEM>>>(ahi, alo, yth, U, nullptr, h, 1);

    for (int i = 0; i < LBLK; i++) {
        const float* W1  = blk_W1  + (size_t)i * HID * HID;
        const float* Wl1 = blk_Wl1 + (size_t)i * HID * HID;
        const float* b1  = blk_b1  + (size_t)i * HID;
        const float* W2  = blk_W2  + (size_t)i * HID * HID;
        const float* Wl2 = blk_Wl2 + (size_t)i * HID * HID;
        const float* b2  = blk_b2  + (size_t)i * HID;

        // t = relu(gconv(h))
        proj_fused<<<gproj, blk, PROJ_SMEM>>>(h, HID, W1, Wl1, b1, yth, U);
        adj_mma<<<gmma, blk512, MMA_SMEM>>>(ahi, alo, yth, U, nullptr, t, 1);

        // h = (h + relu(gconv(t))) * 0.5
        proj_fused<<<gproj, blk, PROJ_SMEM>>>(t, HID, W2, Wl2, b2, yth, U);
        adj_mma<<<gmma, blk512, MMA_SMEM>>>(ahi, alo, yth, U, h, h, 2);
    }

    // output head: x_out = adj @ (h@out_W) + h@out_Wl + out_b
    out_proj<<<NN / 256, blk>>>(h, out_W, out_Wl, out_b, Y3, U3);
    adj_small<<<512, blk>>>(adj, Y3, U3, out);

    // second output: h
    cudaMemcpyAsync(out + (size_t)NN * OUT_DIM, h,
                    (size_t)NN * HID * sizeof(float),
                    cudaMemcpyDeviceToDevice, 0);
}

// round 16
// speedup vs baseline: 1.2462x; 1.2462x over previous
#include <cuda_runtime.h>
#include <cuda_fp16.h>
#include <cstdint>

// Problem constants
#define NN      8192
#define IN_DIM  256
#define HID     192
#define OUT_DIM 3
#define LBLK    6

// SIMT projection GEMM tiling (BM=64, best known)
#define BM 64
#define BN 192
#define BK 16
#define TM 4
#define TN 12

// ---------------------------------------------------------------------------
// Scratch (device globals — no allocation allowed)
// ---------------------------------------------------------------------------
__device__ float g_h [NN * HID];
__device__ float g_t [NN * HID];
__device__ float g_U [NN * HID];
__device__ float g_Y3[NN * OUT_DIM];
__device__ float g_U3[NN * OUT_DIM];
__device__ float g_dummy[32];
__device__ __half g_adj_hi[(size_t)NN * NN];   // 128 MB (fp16 hi)
__device__ __half g_adj_lo[(size_t)NN * NN];   // 128 MB (fp16 residual)
__device__ __half g_yt_hi[HID * NN];           // Y^T fp16 (k-contiguous)

// ---------------------------------------------------------------------------
// helpers
// ---------------------------------------------------------------------------
__device__ __forceinline__ uint32_t smem_u32(const void* p) {
    uint32_t a;
    asm("{ .reg .u64 t; cvta.to.shared.u64 t, %1; cvt.u32.u64 %0, t; }"
        : "=r"(a) : "l"(p));
    return a;
}
#define SWZ(o) ((o) ^ (((o) >> 3) & 0x70))

__device__ __forceinline__ void cp_async16(uint32_t dst, const void* src) {
    asm volatile("cp.async.cg.shared.global [%0], [%1], 16;"
                 :: "r"(dst), "l"(src) : "memory");
}
__device__ __forceinline__ void cp_commit() {
    asm volatile("cp.async.commit_group;" ::: "memory");
}
template <int N>
__device__ __forceinline__ void cp_wait() {
    asm volatile("cp.async.wait_group %0;" :: "n"(N) : "memory");
}
__device__ __forceinline__ void ldmx4(uint32_t* r, uint32_t addr) {
    asm volatile("ldmatrix.sync.aligned.m8n8.x4.shared.b16 {%0,%1,%2,%3}, [%4];"
                 : "=r"(r[0]), "=r"(r[1]), "=r"(r[2]), "=r"(r[3]) : "r"(addr));
}
__device__ __forceinline__ void ldmx2(uint32_t* r, uint32_t addr) {
    asm volatile("ldmatrix.sync.aligned.m8n8.x2.shared.b16 {%0,%1}, [%2];"
                 : "=r"(r[0]), "=r"(r[1]) : "r"(addr));
}
__device__ __forceinline__ void mma16816(float* c, const uint32_t* a,
                                         uint32_t b0, uint32_t b1) {
    asm volatile(
        "mma.sync.aligned.m16n8k16.row.col.f32.f16.f16.f32 "
        "{%0,%1,%2,%3}, {%4,%5,%6,%7}, {%8,%9}, {%0,%1,%2,%3};"
        : "+f"(c[0]), "+f"(c[1]), "+f"(c[2]), "+f"(c[3])
        : "r"(a[0]), "r"(a[1]), "r"(a[2]), "r"(a[3]), "r"(b0), "r"(b1));
}

// ---------------------------------------------------------------------------
// dummy launch (shifts ncu -s 5 capture window onto adj_mma)
// ---------------------------------------------------------------------------
__global__ void dummy_k() { g_dummy[threadIdx.x] = 0.f; }

// ---------------------------------------------------------------------------
// adj fp32 -> fp16 hi/lo split
// ---------------------------------------------------------------------------
__global__ __launch_bounds__(256) void convert_adj(const float* __restrict__ adj)
{
    size_t i = (size_t)blockIdx.x * 256 + threadIdx.x;   // float4 index
    float4 v = ((const float4*)adj)[i];
    __half h0 = __float2half_rn(v.x);
    __half h1 = __float2half_rn(v.y);
    __half h2 = __float2half_rn(v.z);
    __half h3 = __float2half_rn(v.w);
    __half l0 = __float2half_rn(v.x - __half2float(h0));
    __half l1 = __float2half_rn(v.y - __half2float(h1));
    __half l2 = __float2half_rn(v.z - __half2float(h2));
    __half l3 = __float2half_rn(v.w - __half2float(h3));
    uint32_t hw0 = (uint32_t)(*(unsigned short*)&h0) | ((uint32_t)(*(unsigned short*)&h1) << 16);
    uint32_t hw1 = (uint32_t)(*(unsigned short*)&h2) | ((uint32_t)(*(unsigned short*)&h3) << 16);
    uint32_t lw0 = (uint32_t)(*(unsigned short*)&l0) | ((uint32_t)(*(unsigned short*)&l1) << 16);
    uint32_t lw1 = (uint32_t)(*(unsigned short*)&l2) | ((uint32_t)(*(unsigned short*)&l3) << 16);
    ((uint2*)g_adj_hi)[i] = make_uint2(hw0, hw1);
    ((uint2*)g_adj_lo)[i] = make_uint2(lw0, lw1);
}

// ---------------------------------------------------------------------------
// HMMA adj GEMM, fp16 2-pass, 2 CTAs/SM:
//   out = epilogue( (Ahi + Alo) @ fp16(Y) )
//   mode 1: out = relu(acc + U);  mode 2: out = (R + relu(acc + U)) * 0.5
// grid 256: bx>>1 -> 64-row strip, bx&1 -> 96-col half.
// 256 threads = 8 warps, warp grid 2(M)x4(N), warp tile 32x24.
// 3-stage cp.async ring, 28KB/stage -> 84KB/CTA -> 2 CTAs resident per SM.
// ---------------------------------------------------------------------------
#define A_HI_OFF 0
#define A_LO_OFF 8192
#define B_HI_OFF 16384
#define ST_BYTES 28672
#define N_STAGE  3
#define MMA_SMEM (N_STAGE * ST_BYTES)   // 86016

__global__ __launch_bounds__(256, 2) void adj_mma(
    const __half* __restrict__ Ahi, const __half* __restrict__ Alo,
    const __half* __restrict__ Bhi,
    const float* __restrict__ U, const float* __restrict__ R,
    float* __restrict__ out, int mode)
{
    extern __shared__ __align__(1024) char smem[];
    const uint32_t sb = smem_u32(smem);
    const int tid  = threadIdx.x;
    const int warp = tid >> 5;
    const int lane = tid & 31;
    const int m0   = (blockIdx.x >> 1) * 64;
    const int n0   = (blockIdx.x & 1) * 96;
    const int wm   = warp & 1;    // 2 groups of 32 rows
    const int wn   = warp >> 1;   // 4 groups of 24 cols

    float acc[2][3][4];
#pragma unroll
    for (int mt = 0; mt < 2; mt++)
#pragma unroll
        for (int nt = 0; nt < 3; nt++)
#pragma unroll
            for (int q = 0; q < 4; q++) acc[mt][nt][q] = 0.f;

    // ldmatrix per-lane offsets (128B rows)
    int a_off[2], xa[2];
#pragma unroll
    for (int mt = 0; mt < 2; mt++) {
        int r = wm * 32 + mt * 16 + (lane & 15);
        a_off[mt] = r * 128 + (lane >> 4) * 16;
        xa[mt] = (a_off[mt] >> 3) & 0x70;
    }
    int b4_off, xb4;
    {
        int r = wn * 24 + (lane & 7) + ((lane >> 4) << 3);
        b4_off = r * 128 + ((lane >> 3) & 1) * 16;
        xb4 = (b4_off >> 3) & 0x70;
    }
    int b2_off, xb2;
    {
        int l = lane & 15;
        int r = wn * 24 + 16 + (l & 7);
        b2_off = r * 128 + ((l >> 3) & 1) * 16;
        xb2 = (b2_off >> 3) & 0x70;
    }

    auto issue = [&](int c) {
        const uint32_t stage = sb + (uint32_t)(c % N_STAGE) * ST_BYTES;
        const int k0 = c << 6;
        // A: 64 rows x 8 float4 = 512 float4 per array; 2 per thread
#pragma unroll
        for (int p = 0; p < 2; p++) {
            int f = p * 256 + tid, r = f >> 3, j = f & 7;
            size_t src = (size_t)(m0 + r) * NN + k0 + j * 8;
            uint32_t d = SWZ((uint32_t)(r * 128 + j * 16));
            cp_async16(stage + A_HI_OFF + d, Ahi + src);
            cp_async16(stage + A_LO_OFF + d, Alo + src);
        }
        // B: 96 rows x 8 float4 = 768 float4; 3 per thread
#pragma unroll
        for (int p = 0; p < 3; p++) {
            int f = p * 256 + tid, r = f >> 3, j = f & 7;
            size_t src = (size_t)(n0 + r) * NN + k0 + j * 8;
            uint32_t d = SWZ((uint32_t)(r * 128 + j * 16));
            cp_async16(stage + B_HI_OFF + d, Bhi + src);
        }
        cp_commit();
    };

    const int NC = NN / 64;   // 128 chunks
    issue(0);
    issue(1);
    for (int c = 0; c < NC; c++) {
        if (c + 1 < NC) cp_wait<1>(); else cp_wait<0>();
        __syncthreads();
        if (c + 2 < NC) issue(c + 2);
        const uint32_t base = sb + (uint32_t)(c % N_STAGE) * ST_BYTES;
#pragma unroll
        for (int ks = 0; ks < 4; ks++) {
            const int kb = ks * 32;
            uint32_t ah[2][4], al[2][4], bh4[4], bh2[2];
#pragma unroll
            for (int mt = 0; mt < 2; mt++) {
                uint32_t d = (uint32_t)((a_off[mt] + kb) ^ xa[mt]);
                ldmx4(ah[mt], base + A_HI_OFF + d);
                ldmx4(al[mt], base + A_LO_OFF + d);
            }
            {
                uint32_t d = (uint32_t)((b4_off + kb) ^ xb4);
                ldmx4(bh4, base + B_HI_OFF + d);
            }
            {
                uint32_t d = (uint32_t)((b2_off + kb) ^ xb2);
                ldmx2(bh2, base + B_HI_OFF + d);
            }
            // pass-major: hi then lo
#pragma unroll
            for (int mt = 0; mt < 2; mt++) {
                mma16816(acc[mt][0], ah[mt], bh4[0], bh4[1]);
                mma16816(acc[mt][1], ah[mt], bh4[2], bh4[3]);
                mma16816(acc[mt][2], ah[mt], bh2[0], bh2[1]);
            }
#pragma unroll
            for (int mt = 0; mt < 2; mt++) {
                mma16816(acc[mt][0], al[mt], bh4[0], bh4[1]);
                mma16816(acc[mt][1], al[mt], bh4[2], bh4[3]);
                mma16816(acc[mt][2], al[mt], bh2[0], bh2[1]);
            }
        }
        __syncthreads();
    }

    // epilogue
    const int tr = lane >> 2;
    const int tc = (lane & 3) * 2;
#pragma unroll
    for (int mt = 0; mt < 2; mt++)
#pragma unroll
        for (int nt = 0; nt < 3; nt++)
#pragma unroll
            for (int hh = 0; hh < 2; hh++) {
                const int row = m0 + wm * 32 + mt * 16 + tr + hh * 8;
                const int col = n0 + wn * 24 + nt * 8 + tc;
                const size_t idx = (size_t)row * HID + col;
                float v0 = acc[mt][nt][hh * 2 + 0];
                float v1 = acc[mt][nt][hh * 2 + 1];
                const float2 u = *(const float2*)(U + idx);
                v0 = fmaxf(v0 + u.x, 0.f);
                v1 = fmaxf(v1 + u.y, 0.f);
                if (mode == 2) {
                    const float2 rr = *(const float2*)(R + idx);
                    v0 = (rr.x + v0) * 0.5f;
                    v1 = (rr.y + v1) * 0.5f;
                }
                *(float2*)(out + idx) = make_float2(v0, v1);
            }
}

// ---------------------------------------------------------------------------
// Fused projection (BM=64, best known): Y = A@W (-> transposed fp16),
//                   U = A@Wl + bias (fp32)
// ---------------------------------------------------------------------------
#define YT_STRIDE 72
#define PROJ_SMEM ((2 * BK * (BM + 4) + 2 * 2 * BK * BN) * 4)   // 57856

__global__ __launch_bounds__(256, 1) void proj_fused(
    const float* __restrict__ A, int K,
    const float* __restrict__ W,
    const float* __restrict__ Wl,
    const float* __restrict__ bias,
    __half* __restrict__ yth,
    float* __restrict__ Uo)
{
    extern __shared__ __align__(16) float ps[];
    float* As  = ps;                              // [2][BK][BM+4]
    float* BsY = ps + 2 * BK * (BM + 4);          // [2][BK][BN]
    float* BsU = BsY + 2 * BK * BN;               // [2][BK][BN]

    const int tid = threadIdx.x;
    const int m0  = blockIdx.x * BM;

    const int am = tid >> 2;
    const int ak = (tid & 3) * 4;
    const float* Aptr = A + (size_t)(m0 + am) * (size_t)K + ak;

    const int tx = tid & 15;
    const int ty = tid >> 4;

    float accY[TM][TN], accU[TM][TN];
#pragma unroll
    for (int i = 0; i < TM; i++)
#pragma unroll
        for (int j = 0; j < TN; j++) { accY[i][j] = 0.f; accU[i][j] = 0.f; }

    const int nk = K / BK;

    auto loadA = [&](int buf, int k0) {
        float4 v = *(const float4*)(Aptr + k0);
        float* dst = As + buf * BK * (BM + 4);
        dst[(ak + 0) * (BM + 4) + am] = v.x;
        dst[(ak + 1) * (BM + 4) + am] = v.y;
        dst[(ak + 2) * (BM + 4) + am] = v.z;
        dst[(ak + 3) * (BM + 4) + am] = v.w;
    };
    auto loadB = [&](int buf, int k0) {
#pragma unroll
        for (int i = 0; i < 3; i++) {
            int f  = i * 256 + tid;
            int kr = f / 48;
            int c4 = f % 48;
            size_t src = (size_t)(k0 + kr) * BN + c4 * 4;
            *(float4*)(BsY + buf * BK * BN + kr * BN + c4 * 4) = *(const float4*)(W  + src);
            *(float4*)(BsU + buf * BK * BN + kr * BN + c4 * 4) = *(const float4*)(Wl + src);
        }
    };

    loadA(0, 0);
    loadB(0, 0);
    __syncthreads();

    int buf = 0;
    for (int kb = 0; kb < nk; kb++) {
        if (kb + 1 < nk) {
            int k0n = (kb + 1) * BK;
            loadA(buf ^ 1, k0n);
            loadB(buf ^ 1, k0n);
        }
        const float* Ab = As + buf * BK * (BM + 4);
        const float* BY = BsY + buf * BK * BN;
        const float* BU = BsU + buf * BK * BN;
#pragma unroll
        for (int k = 0; k < BK; k++) {
            float a[TM];
            float4 av = *(const float4*)(Ab + k * (BM + 4) + ty * 4);
            a[0] = av.x; a[1] = av.y; a[2] = av.z; a[3] = av.w;
            float by[TN], bu[TN];
#pragma unroll
            for (int q = 0; q < 3; q++) {
                float4 v = *(const float4*)(BY + k * BN + tx * 12 + q * 4);
                by[q * 4 + 0] = v.x; by[q * 4 + 1] = v.y;
                by[q * 4 + 2] = v.z; by[q * 4 + 3] = v.w;
                float4 u = *(const float4*)(BU + k * BN + tx * 12 + q * 4);
                bu[q * 4 + 0] = u.x; bu[q * 4 + 1] = u.y;
                bu[q * 4 + 2] = u.z; bu[q * 4 + 3] = u.w;
            }
#pragma unroll
            for (int i = 0; i < TM; i++)
#pragma unroll
                for (int j = 0; j < TN; j++) {
                    accY[i][j] += a[i] * by[j];
                    accU[i][j] += a[i] * bu[j];
                }
        }
        __syncthreads();
        buf ^= 1;
    }

    float bv[TN];
#pragma unroll
    for (int j = 0; j < TN; j++) bv[j] = bias[tx * 12 + j];

    // U output (fp32, coalesced row-major)
#pragma unroll
    for (int i = 0; i < TM; i++) {
        const int row = m0 + ty * 4 + i;
        const size_t base = (size_t)row * BN + tx * 12;
        float4* o = (float4*)(Uo + base);
        o[0] = make_float4(accU[i][0] + bv[0], accU[i][1] + bv[1], accU[i][2]  + bv[2],  accU[i][3]  + bv[3]);
        o[1] = make_float4(accU[i][4] + bv[4], accU[i][5] + bv[5], accU[i][6]  + bv[6],  accU[i][7]  + bv[7]);
        o[2] = make_float4(accU[i][8] + bv[8], accU[i][9] + bv[9], accU[i][10] + bv[10], accU[i][11] + bv[11]);
    }

    // Y output: stage transposed fp16 in smem, then coalesced flush
    __syncthreads();   // main-loop smem dead; reuse
    __half* sh = (__half*)ps;                 // [BN][YT_STRIDE]
#pragma unroll
    for (int i = 0; i < TM; i++) {
        const int r = ty * 4 + i;     // local row 0..63
#pragma unroll
        for (int j = 0; j < TN; j++) {
            const int col = tx * 12 + j;
            sh[col * YT_STRIDE + r] = __float2half_rn(accY[i][j]);
        }
    }
    __syncthreads();
    // flush: 192 cols x 64 rows, 2 fp16 per thread-step
    for (int idx = tid; idx < BN * (BM / 2); idx += 256) {
        const int col = idx >> 5;
        const int r2  = (idx & 31) * 2;
        uint32_t vh = (uint32_t)*(const unsigned short*)&sh[col * YT_STRIDE + r2]
                    | ((uint32_t)*(const unsigned short*)&sh[col * YT_STRIDE + r2 + 1] << 16);
        *(uint32_t*)(yth + (size_t)col * NN + m0 + r2) = vh;
    }
}

// ---------------------------------------------------------------------------
// Output head
// ---------------------------------------------------------------------------
__global__ __launch_bounds__(256) void out_proj(
    const float* __restrict__ h,
    const float* __restrict__ W,
    const float* __restrict__ Wl,
    const float* __restrict__ b,
    float* __restrict__ Y3,
    float* __restrict__ U3)
{
    __shared__ float sW[HID * OUT_DIM];
    __shared__ float sWl[HID * OUT_DIM];
    for (int i = threadIdx.x; i < HID * OUT_DIM; i += blockDim.x) {
        sW[i]  = W[i];
        sWl[i] = Wl[i];
    }
    __syncthreads();

    int m = blockIdx.x * blockDim.x + threadIdx.x;
    if (m >= NN) return;

    const float* hr = h + (size_t)m * HID;
    float a0 = 0.f, a1 = 0.f, a2 = 0.f;
    float l0 = 0.f, l1 = 0.f, l2 = 0.f;
#pragma unroll 4
    for (int k = 0; k < HID; k++) {
        float hv = hr[k];
        a0 += hv * sW[k * 3 + 0];
        a1 += hv * sW[k * 3 + 1];
        a2 += hv * sW[k * 3 + 2];
        l0 += hv * sWl[k * 3 + 0];
        l1 += hv * sWl[k * 3 + 1];
        l2 += hv * sWl[k * 3 + 2];
    }
    Y3[m * 3 + 0] = a0; Y3[m * 3 + 1] = a1; Y3[m * 3 + 2] = a2;
    U3[m * 3 + 0] = l0 + b[0];
    U3[m * 3 + 1] = l1 + b[1];
    U3[m * 3 + 2] = l2 + b[2];
}

__global__ __launch_bounds__(256) void adj_small(
    const float* __restrict__ adj,
    const float* __restrict__ Y3,
    const float* __restrict__ U3,
    float* __restrict__ out)
{
    const int lane   = threadIdx.x & 31;
    const int warp   = (blockIdx.x * blockDim.x + threadIdx.x) >> 5;
    const int nwarps = (gridDim.x * blockDim.x) >> 5;

    for (int m = warp; m < NN; m += nwarps) {
        const float4* ar = (const float4*)(adj + (size_t)m * NN);
        float a0 = 0.f, a1 = 0.f, a2 = 0.f;
        for (int f = lane; f < NN / 4; f += 32) {
            float4 v = ar[f];
            int k = f * 4;
            a0 += v.x * Y3[(k + 0) * 3 + 0] + v.y * Y3[(k + 1) * 3 + 0]
                + v.z * Y3[(k + 2) * 3 + 0] + v.w * Y3[(k + 3) * 3 + 0];
            a1 += v.x * Y3[(k + 0) * 3 + 1] + v.y * Y3[(k + 1) * 3 + 1]
                + v.z * Y3[(k + 2) * 3 + 1] + v.w * Y3[(k + 3) * 3 + 1];
            a2 += v.x * Y3[(k + 0) * 3 + 2] + v.y * Y3[(k + 1) * 3 + 2]
                + v.z * Y3[(k + 2) * 3 + 2] + v.w * Y3[(k + 3) * 3 + 2];
        }
#pragma unroll
        for (int off = 16; off > 0; off >>= 1) {
            a0 += __shfl_down_sync(0xffffffffu, a0, off);
            a1 += __shfl_down_sync(0xffffffffu, a1, off);
            a2 += __shfl_down_sync(0xffffffffu, a2, off);
        }
        if (lane == 0) {
            out[m * 3 + 0] = a0 + U3[m * 3 + 0];
            out[m * 3 + 1] = a1 + U3[m * 3 + 1];
            out[m * 3 + 2] = a2 + U3[m * 3 + 2];
        }
    }
}

// ---------------------------------------------------------------------------
extern "C" void kernel_launch(void* const* d_in, const int* in_sizes, int n_in,
                              void* d_out, int out_size)
{
    const float* x      = (const float*)d_in[0];
    const float* adj    = (const float*)d_in[1];
    const float* in_W   = (const float*)d_in[2];
    const float* in_Wl  = (const float*)d_in[3];
    const float* in_b   = (const float*)d_in[4];
    const float* blk_W1  = (const float*)d_in[5];
    const float* blk_Wl1 = (const float*)d_in[6];
    const float* blk_b1  = (const float*)d_in[7];
    const float* blk_W2  = (const float*)d_in[8];
    const float* blk_Wl2 = (const float*)d_in[9];
    const float* blk_b2  = (const float*)d_in[10];
    const float* out_W  = (const float*)d_in[11];
    const float* out_Wl = (const float*)d_in[12];
    const float* out_b  = (const float*)d_in[13];
    float* out = (float*)d_out;

    float *h, *t, *U, *Y3, *U3;
    __half *ahi, *alo, *yth;
    cudaGetSymbolAddress((void**)&h,   g_h);
    cudaGetSymbolAddress((void**)&t,   g_t);
    cudaGetSymbolAddress((void**)&U,   g_U);
    cudaGetSymbolAddress((void**)&Y3,  g_Y3);
    cudaGetSymbolAddress((void**)&U3,  g_U3);
    cudaGetSymbolAddress((void**)&ahi, g_adj_hi);
    cudaGetSymbolAddress((void**)&alo, g_adj_lo);
    cudaGetSymbolAddress((void**)&yth, g_yt_hi);

    cudaFuncSetAttribute(adj_mma,    cudaFuncAttributeMaxDynamicSharedMemorySize, MMA_SMEM);
    cudaFuncSetAttribute(proj_fused, cudaFuncAttributeMaxDynamicSharedMemorySize, PROJ_SMEM);

    const dim3 blk(256);
    const dim3 gproj(NN / BM);   // 128
    const dim3 gmma(256);

    // shift ncu capture (-s 5) so launch #6 is adj_mma
    dummy_k<<<1, 32>>>();

    // split adj into fp16 hi/lo
    convert_adj<<<NN * (NN / 4) / 256, blk>>>(adj);

    // input gconv: h = relu(adj @ (x@in_W) + x@in_Wl + in_b)
    proj_fused<<<gproj, blk, PROJ_SMEM>>>(x, IN_DIM, in_W, in_Wl, in_b, yth, U);
    adj_mma<<<gmma, blk, MMA_SMEM>>>(ahi, alo, yth, U, nullptr, h, 1);

    for (int i = 0; i < LBLK; i++) {
        const float* W1  = blk_W1  + (size_t)i * HID * HID;
        const float* Wl1 = blk_Wl1 + (size_t)i * HID * HID;
        const float* b1  = blk_b1  + (size_t)i * HID;
        const float* W2  = blk_W2  + (size_t)i * HID * HID;
        const float* Wl2 = blk_Wl2 + (size_t)i * HID * HID;
        const float* b2  = blk_b2  + (size_t)i * HID;

        // t = relu(gconv(h))
        proj_fused<<<gproj, blk, PROJ_SMEM>>>(h, HID, W1, Wl1, b1, yth, U);
        adj_mma<<<gmma, blk, MMA_SMEM>>>(ahi, alo, yth, U, nullptr, t, 1);

        // h = (h + relu(gconv(t))) * 0.5
        proj_fused<<<gproj, blk, PROJ_SMEM>>>(t, HID, W2, Wl2, b2, yth, U);
        adj_mma<<<gmma, blk, MMA_SMEM>>>(ahi, alo, yth, U, h, h, 2);
    }

    // output head: x_out = adj @ (h@out_W) + h@out_Wl + out_b
    out_proj<<<NN / 256, blk>>>(h, out_W, out_Wl, out_b, Y3, U3);
    adj_small<<<512, blk>>>(adj, Y3, U3, out);

    // second output: h
    cudaMemcpyAsync(out + (size_t)NN * OUT_DIM, h,
                    (size_t)NN * HID * sizeof(float),
                    cudaMemcpyDeviceToDevice, 0);
}

// round 17
// speedup vs baseline: 1.8140x; 1.4557x over previous
#include <cuda_runtime.h>
#include <cuda_fp16.h>
#include <cstdint>

// Problem constants
#define NN      8192
#define IN_DIM  256
#define HID     192
#define OUT_DIM 3
#define LBLK    6

// SIMT projection GEMM tiling (BM=64, best known)
#define BM 64
#define BN 192
#define BK 16
#define TM 4
#define TN 12

// ---------------------------------------------------------------------------
// Scratch (device globals — no allocation allowed)
// ---------------------------------------------------------------------------
__device__ float g_h [NN * HID];
__device__ float g_t [NN * HID];
__device__ float g_U [NN * HID];
__device__ float g_Y3[NN * OUT_DIM];
__device__ float g_U3[NN * OUT_DIM];
__device__ float g_dummy[32];
__device__ __half g_adj_hi[(size_t)NN * NN];   // 128 MB (fp16)
__device__ __half g_yt_hi[HID * NN];           // Y^T fp16 (k-contiguous)

// ---------------------------------------------------------------------------
// helpers
// ---------------------------------------------------------------------------
__device__ __forceinline__ uint32_t smem_u32(const void* p) {
    uint32_t a;
    asm("{ .reg .u64 t; cvta.to.shared.u64 t, %1; cvt.u32.u64 %0, t; }"
        : "=r"(a) : "l"(p));
    return a;
}
#define SWZ(o) ((o) ^ (((o) >> 3) & 0x70))

__device__ __forceinline__ void cp_async16(uint32_t dst, const void* src) {
    asm volatile("cp.async.cg.shared.global [%0], [%1], 16;"
                 :: "r"(dst), "l"(src) : "memory");
}
__device__ __forceinline__ void cp_commit() {
    asm volatile("cp.async.commit_group;" ::: "memory");
}
template <int N>
__device__ __forceinline__ void cp_wait() {
    asm volatile("cp.async.wait_group %0;" :: "n"(N) : "memory");
}
__device__ __forceinline__ void ldmx4(uint32_t* r, uint32_t addr) {
    asm volatile("ldmatrix.sync.aligned.m8n8.x4.shared.b16 {%0,%1,%2,%3}, [%4];"
                 : "=r"(r[0]), "=r"(r[1]), "=r"(r[2]), "=r"(r[3]) : "r"(addr));
}
__device__ __forceinline__ void ldmx2(uint32_t* r, uint32_t addr) {
    asm volatile("ldmatrix.sync.aligned.m8n8.x2.shared.b16 {%0,%1}, [%2];"
                 : "=r"(r[0]), "=r"(r[1]) : "r"(addr));
}
__device__ __forceinline__ void mma16816(float* c, const uint32_t* a,
                                         uint32_t b0, uint32_t b1) {
    asm volatile(
        "mma.sync.aligned.m16n8k16.row.col.f32.f16.f16.f32 "
        "{%0,%1,%2,%3}, {%4,%5,%6,%7}, {%8,%9}, {%0,%1,%2,%3};"
        : "+f"(c[0]), "+f"(c[1]), "+f"(c[2]), "+f"(c[3])
        : "r"(a[0]), "r"(a[1]), "r"(a[2]), "r"(a[3]), "r"(b0), "r"(b1));
}

// ---------------------------------------------------------------------------
// dummy launch (keeps ncu -s 5 capture window on adj_mma)
// ---------------------------------------------------------------------------
__global__ void dummy_k() { g_dummy[threadIdx.x] = 0.f; }

// ---------------------------------------------------------------------------
// adj fp32 -> fp16
// ---------------------------------------------------------------------------
__global__ __launch_bounds__(256) void convert_adj(const float* __restrict__ adj)
{
    size_t i = (size_t)blockIdx.x * 256 + threadIdx.x;   // float4 index
    float4 v = ((const float4*)adj)[i];
    __half h0 = __float2half_rn(v.x);
    __half h1 = __float2half_rn(v.y);
    __half h2 = __float2half_rn(v.z);
    __half h3 = __float2half_rn(v.w);
    uint32_t hw0 = (uint32_t)(*(unsigned short*)&h0) | ((uint32_t)(*(unsigned short*)&h1) << 16);
    uint32_t hw1 = (uint32_t)(*(unsigned short*)&h2) | ((uint32_t)(*(unsigned short*)&h3) << 16);
    ((uint2*)g_adj_hi)[i] = make_uint2(hw0, hw1);
}

// ---------------------------------------------------------------------------
// HMMA adj GEMM, pure fp16 single-pass, up to 3 CTAs/SM:
//   out = epilogue( fp16(adj) @ fp16(Y) ), fp32 accumulate
//   mode 1: out = relu(acc + U);  mode 2: out = (R + relu(acc + U)) * 0.5
// grid 256: bx>>1 -> 64-row strip, bx&1 -> 96-col half.
// 256 threads = 8 warps, warp grid 2(M)x4(N), warp tile 32x24.
// 3-stage cp.async ring, 20KB/stage -> 60KB/CTA.
// ---------------------------------------------------------------------------
#define A_OFF 0
#define B_OFF 8192
#define ST_BYTES 20480
#define N_STAGE  3
#define MMA_SMEM (N_STAGE * ST_BYTES)   // 61440

__global__ __launch_bounds__(256, 3) void adj_mma(
    const __half* __restrict__ Ahi,
    const __half* __restrict__ Bhi,
    const float* __restrict__ U, const float* __restrict__ R,
    float* __restrict__ out, int mode)
{
    extern __shared__ __align__(1024) char smem[];
    const uint32_t sb = smem_u32(smem);
    const int tid  = threadIdx.x;
    const int warp = tid >> 5;
    const int lane = tid & 31;
    const int m0   = (blockIdx.x >> 1) * 64;
    const int n0   = (blockIdx.x & 1) * 96;
    const int wm   = warp & 1;    // 2 groups of 32 rows
    const int wn   = warp >> 1;   // 4 groups of 24 cols

    float acc[2][3][4];
#pragma unroll
    for (int mt = 0; mt < 2; mt++)
#pragma unroll
        for (int nt = 0; nt < 3; nt++)
#pragma unroll
            for (int q = 0; q < 4; q++) acc[mt][nt][q] = 0.f;

    // ldmatrix per-lane offsets (128B rows)
    int a_off[2], xa[2];
#pragma unroll
    for (int mt = 0; mt < 2; mt++) {
        int r = wm * 32 + mt * 16 + (lane & 15);
        a_off[mt] = r * 128 + (lane >> 4) * 16;
        xa[mt] = (a_off[mt] >> 3) & 0x70;
    }
    int b4_off, xb4;
    {
        int r = wn * 24 + (lane & 7) + ((lane >> 4) << 3);
        b4_off = r * 128 + ((lane >> 3) & 1) * 16;
        xb4 = (b4_off >> 3) & 0x70;
    }
    int b2_off, xb2;
    {
        int l = lane & 15;
        int r = wn * 24 + 16 + (l & 7);
        b2_off = r * 128 + ((l >> 3) & 1) * 16;
        xb2 = (b2_off >> 3) & 0x70;
    }

    auto issue = [&](int c) {
        const uint32_t stage = sb + (uint32_t)(c % N_STAGE) * ST_BYTES;
        const int k0 = c << 6;
        // A: 64 rows x 8 float4 = 512 float4; 2 per thread
#pragma unroll
        for (int p = 0; p < 2; p++) {
            int f = p * 256 + tid, r = f >> 3, j = f & 7;
            size_t src = (size_t)(m0 + r) * NN + k0 + j * 8;
            uint32_t d = SWZ((uint32_t)(r * 128 + j * 16));
            cp_async16(stage + A_OFF + d, Ahi + src);
        }
        // B: 96 rows x 8 float4 = 768 float4; 3 per thread
#pragma unroll
        for (int p = 0; p < 3; p++) {
            int f = p * 256 + tid, r = f >> 3, j = f & 7;
            size_t src = (size_t)(n0 + r) * NN + k0 + j * 8;
            uint32_t d = SWZ((uint32_t)(r * 128 + j * 16));
            cp_async16(stage + B_OFF + d, Bhi + src);
        }
        cp_commit();
    };

    const int NC = NN / 64;   // 128 chunks
    issue(0);
    issue(1);
    for (int c = 0; c < NC; c++) {
        if (c + 1 < NC) cp_wait<1>(); else cp_wait<0>();
        __syncthreads();
        if (c + 2 < NC) issue(c + 2);
        const uint32_t base = sb + (uint32_t)(c % N_STAGE) * ST_BYTES;
#pragma unroll
        for (int ks = 0; ks < 4; ks++) {
            const int kb = ks * 32;
            uint32_t ah[2][4], bh4[4], bh2[2];
#pragma unroll
            for (int mt = 0; mt < 2; mt++) {
                uint32_t d = (uint32_t)((a_off[mt] + kb) ^ xa[mt]);
                ldmx4(ah[mt], base + A_OFF + d);
            }
            {
                uint32_t d = (uint32_t)((b4_off + kb) ^ xb4);
                ldmx4(bh4, base + B_OFF + d);
            }
            {
                uint32_t d = (uint32_t)((b2_off + kb) ^ xb2);
                ldmx2(bh2, base + B_OFF + d);
            }
#pragma unroll
            for (int mt = 0; mt < 2; mt++) {
                mma16816(acc[mt][0], ah[mt], bh4[0], bh4[1]);
                mma16816(acc[mt][1], ah[mt], bh4[2], bh4[3]);
                mma16816(acc[mt][2], ah[mt], bh2[0], bh2[1]);
            }
        }
        __syncthreads();
    }

    // epilogue
    const int tr = lane >> 2;
    const int tc = (lane & 3) * 2;
#pragma unroll
    for (int mt = 0; mt < 2; mt++)
#pragma unroll
        for (int nt = 0; nt < 3; nt++)
#pragma unroll
            for (int hh = 0; hh < 2; hh++) {
                const int row = m0 + wm * 32 + mt * 16 + tr + hh * 8;
                const int col = n0 + wn * 24 + nt * 8 + tc;
                const size_t idx = (size_t)row * HID + col;
                float v0 = acc[mt][nt][hh * 2 + 0];
                float v1 = acc[mt][nt][hh * 2 + 1];
                const float2 u = *(const float2*)(U + idx);
                v0 = fmaxf(v0 + u.x, 0.f);
                v1 = fmaxf(v1 + u.y, 0.f);
                if (mode == 2) {
                    const float2 rr = *(const float2*)(R + idx);
                    v0 = (rr.x + v0) * 0.5f;
                    v1 = (rr.y + v1) * 0.5f;
                }
                *(float2*)(out + idx) = make_float2(v0, v1);
            }
}

// ---------------------------------------------------------------------------
// Fused projection (BM=64): Y = A@W (-> transposed fp16), U = A@Wl + bias
// ---------------------------------------------------------------------------
#define YT_STRIDE 72
#define PROJ_SMEM ((2 * BK * (BM + 4) + 2 * 2 * BK * BN) * 4)   // 57856

__global__ __launch_bounds__(256, 1) void proj_fused(
    const float* __restrict__ A, int K,
    const float* __restrict__ W,
    const float* __restrict__ Wl,
    const float* __restrict__ bias,
    __half* __restrict__ yth,
    float* __restrict__ Uo)
{
    extern __shared__ __align__(16) float ps[];
    float* As  = ps;                              // [2][BK][BM+4]
    float* BsY = ps + 2 * BK * (BM + 4);          // [2][BK][BN]
    float* BsU = BsY + 2 * BK * BN;               // [2][BK][BN]

    const int tid = threadIdx.x;
    const int m0  = blockIdx.x * BM;

    const int am = tid >> 2;
    const int ak = (tid & 3) * 4;
    const float* Aptr = A + (size_t)(m0 + am) * (size_t)K + ak;

    const int tx = tid & 15;
    const int ty = tid >> 4;

    float accY[TM][TN], accU[TM][TN];
#pragma unroll
    for (int i = 0; i < TM; i++)
#pragma unroll
        for (int j = 0; j < TN; j++) { accY[i][j] = 0.f; accU[i][j] = 0.f; }

    const int nk = K / BK;

    auto loadA = [&](int buf, int k0) {
        float4 v = *(const float4*)(Aptr + k0);
        float* dst = As + buf * BK * (BM + 4);
        dst[(ak + 0) * (BM + 4) + am] = v.x;
        dst[(ak + 1) * (BM + 4) + am] = v.y;
        dst[(ak + 2) * (BM + 4) + am] = v.z;
        dst[(ak + 3) * (BM + 4) + am] = v.w;
    };
    auto loadB = [&](int buf, int k0) {
#pragma unroll
        for (int i = 0; i < 3; i++) {
            int f  = i * 256 + tid;
            int kr = f / 48;
            int c4 = f % 48;
            size_t src = (size_t)(k0 + kr) * BN + c4 * 4;
            *(float4*)(BsY + buf * BK * BN + kr * BN + c4 * 4) = *(const float4*)(W  + src);
            *(float4*)(BsU + buf * BK * BN + kr * BN + c4 * 4) = *(const float4*)(Wl + src);
        }
    };

    loadA(0, 0);
    loadB(0, 0);
    __syncthreads();

    int buf = 0;
    for (int kb = 0; kb < nk; kb++) {
        if (kb + 1 < nk) {
            int k0n = (kb + 1) * BK;
            loadA(buf ^ 1, k0n);
            loadB(buf ^ 1, k0n);
        }
        const float* Ab = As + buf * BK * (BM + 4);
        const float* BY = BsY + buf * BK * BN;
        const float* BU = BsU + buf * BK * BN;
#pragma unroll
        for (int k = 0; k < BK; k++) {
            float a[TM];
            float4 av = *(const float4*)(Ab + k * (BM + 4) + ty * 4);
            a[0] = av.x; a[1] = av.y; a[2] = av.z; a[3] = av.w;
            float by[TN], bu[TN];
#pragma unroll
            for (int q = 0; q < 3; q++) {
                float4 v = *(const float4*)(BY + k * BN + tx * 12 + q * 4);
                by[q * 4 + 0] = v.x; by[q * 4 + 1] = v.y;
                by[q * 4 + 2] = v.z; by[q * 4 + 3] = v.w;
                float4 u = *(const float4*)(BU + k * BN + tx * 12 + q * 4);
                bu[q * 4 + 0] = u.x; bu[q * 4 + 1] = u.y;
                bu[q * 4 + 2] = u.z; bu[q * 4 + 3] = u.w;
            }
#pragma unroll
            for (int i = 0; i < TM; i++)
#pragma unroll
                for (int j = 0; j < TN; j++) {
                    accY[i][j] += a[i] * by[j];
                    accU[i][j] += a[i] * bu[j];
                }
        }
        __syncthreads();
        buf ^= 1;
    }

    float bv[TN];
#pragma unroll
    for (int j = 0; j < TN; j++) bv[j] = bias[tx * 12 + j];

    // U output (fp32, coalesced row-major)
#pragma unroll
    for (int i = 0; i < TM; i++) {
        const int row = m0 + ty * 4 + i;
        const size_t base = (size_t)row * BN + tx * 12;
        float4* o = (float4*)(Uo + base);
        o[0] = make_float4(accU[i][0] + bv[0], accU[i][1] + bv[1], accU[i][2]  + bv[2],  accU[i][3]  + bv[3]);
        o[1] = make_float4(accU[i][4] + bv[4], accU[i][5] + bv[5], accU[i][6]  + bv[6],  accU[i][7]  + bv[7]);
        o[2] = make_float4(accU[i][8] + bv[8], accU[i][9] + bv[9], accU[i][10] + bv[10], accU[i][11] + bv[11]);
    }

    // Y output: stage transposed fp16 in smem, then coalesced flush
    __syncthreads();   // main-loop smem dead; reuse
    __half* sh = (__half*)ps;                 // [BN][YT_STRIDE]
#pragma unroll
    for (int i = 0; i < TM; i++) {
        const int r = ty * 4 + i;     // local row 0..63
#pragma unroll
        for (int j = 0; j < TN; j++) {
            const int col = tx * 12 + j;
            sh[col * YT_STRIDE + r] = __float2half_rn(accY[i][j]);
        }
    }
    __syncthreads();
    // flush: 192 cols x 64 rows, 2 fp16 per thread-step
    for (int idx = tid; idx < BN * (BM / 2); idx += 256) {
        const int col = idx >> 5;
        const int r2  = (idx & 31) * 2;
        uint32_t vh = (uint32_t)*(const unsigned short*)&sh[col * YT_STRIDE + r2]
                    | ((uint32_t)*(const unsigned short*)&sh[col * YT_STRIDE + r2 + 1] << 16);
        *(uint32_t*)(yth + (size_t)col * NN + m0 + r2) = vh;
    }
}

// ---------------------------------------------------------------------------
// Output head
// ---------------------------------------------------------------------------
__global__ __launch_bounds__(256) void out_proj(
    const float* __restrict__ h,
    const float* __restrict__ W,
    const float* __restrict__ Wl,
    const float* __restrict__ b,
    float* __restrict__ Y3,
    float* __restrict__ U3)
{
    __shared__ float sW[HID * OUT_DIM];
    __shared__ float sWl[HID * OUT_DIM];
    for (int i = threadIdx.x; i < HID * OUT_DIM; i += blockDim.x) {
        sW[i]  = W[i];
        sWl[i] = Wl[i];
    }
    __syncthreads();

    int m = blockIdx.x * blockDim.x + threadIdx.x;
    if (m >= NN) return;

    const float* hr = h + (size_t)m * HID;
    float a0 = 0.f, a1 = 0.f, a2 = 0.f;
    float l0 = 0.f, l1 = 0.f, l2 = 0.f;
#pragma unroll 4
    for (int k = 0; k < HID; k++) {
        float hv = hr[k];
        a0 += hv * sW[k * 3 + 0];
        a1 += hv * sW[k * 3 + 1];
        a2 += hv * sW[k * 3 + 2];
        l0 += hv * sWl[k * 3 + 0];
        l1 += hv * sWl[k * 3 + 1];
        l2 += hv * sWl[k * 3 + 2];
    }
    Y3[m * 3 + 0] = a0; Y3[m * 3 + 1] = a1; Y3[m * 3 + 2] = a2;
    U3[m * 3 + 0] = l0 + b[0];
    U3[m * 3 + 1] = l1 + b[1];
    U3[m * 3 + 2] = l2 + b[2];
}

__global__ __launch_bounds__(256) void adj_small(
    const float* __restrict__ adj,
    const float* __restrict__ Y3,
    const float* __restrict__ U3,
    float* __restrict__ out)
{
    const int lane   = threadIdx.x & 31;
    const int warp   = (blockIdx.x * blockDim.x + threadIdx.x) >> 5;
    const int nwarps = (gridDim.x * blockDim.x) >> 5;

    for (int m = warp; m < NN; m += nwarps) {
        const float4* ar = (const float4*)(adj + (size_t)m * NN);
        float a0 = 0.f, a1 = 0.f, a2 = 0.f;
        for (int f = lane; f < NN / 4; f += 32) {
            float4 v = ar[f];
            int k = f * 4;
            a0 += v.x * Y3[(k + 0) * 3 + 0] + v.y * Y3[(k + 1) * 3 + 0]
                + v.z * Y3[(k + 2) * 3 + 0] + v.w * Y3[(k + 3) * 3 + 0];
            a1 += v.x * Y3[(k + 0) * 3 + 1] + v.y * Y3[(k + 1) * 3 + 1]
                + v.z * Y3[(k + 2) * 3 + 1] + v.w * Y3[(k + 3) * 3 + 1];
            a2 += v.x * Y3[(k + 0) * 3 + 2] + v.y * Y3[(k + 1) * 3 + 2]
                + v.z * Y3[(k + 2) * 3 + 2] + v.w * Y3[(k + 3) * 3 + 2];
        }
#pragma unroll
        for (int off = 16; off > 0; off >>= 1) {
            a0 += __shfl_down_sync(0xffffffffu, a0, off);
            a1 += __shfl_down_sync(0xffffffffu, a1, off);
            a2 += __shfl_down_sync(0xffffffffu, a2, off);
        }
        if (lane == 0) {
            out[m * 3 + 0] = a0 + U3[m * 3 + 0];
            out[m * 3 + 1] = a1 + U3[m * 3 + 1];
            out[m * 3 + 2] = a2 + U3[m * 3 + 2];
        }
    }
}

// ---------------------------------------------------------------------------
extern "C" void kernel_launch(void* const* d_in, const int* in_sizes, int n_in,
                              void* d_out, int out_size)
{
    const float* x      = (const float*)d_in[0];
    const float* adj    = (const float*)d_in[1];
    const float* in_W   = (const float*)d_in[2];
    const float* in_Wl  = (const float*)d_in[3];
    const float* in_b   = (const float*)d_in[4];
    const float* blk_W1  = (const float*)d_in[5];
    const float* blk_Wl1 = (const float*)d_in[6];
    const float* blk_b1  = (const float*)d_in[7];
    const float* blk_W2  = (const float*)d_in[8];
    const float* blk_Wl2 = (const float*)d_in[9];
    const float* blk_b2  = (const float*)d_in[10];
    const float* out_W  = (const float*)d_in[11];
    const float* out_Wl = (const float*)d_in[12];
    const float* out_b  = (const float*)d_in[13];
    float* out = (float*)d_out;

    float *h, *t, *U, *Y3, *U3;
    __half *ahi, *yth;
    cudaGetSymbolAddress((void**)&h,   g_h);
    cudaGetSymbolAddress((void**)&t,   g_t);
    cudaGetSymbolAddress((void**)&U,   g_U);
    cudaGetSymbolAddress((void**)&Y3,  g_Y3);
    cudaGetSymbolAddress((void**)&U3,  g_U3);
    cudaGetSymbolAddress((void**)&ahi, g_adj_hi);
    cudaGetSymbolAddress((void**)&yth, g_yt_hi);

    cudaFuncSetAttribute(adj_mma,    cudaFuncAttributeMaxDynamicSharedMemorySize, MMA_SMEM);
    cudaFuncSetAttribute(proj_fused, cudaFuncAttributeMaxDynamicSharedMemorySize, PROJ_SMEM);

    const dim3 blk(256);
    const dim3 gproj(NN / BM);   // 128
    const dim3 gmma(256);

    // shift ncu capture (-s 5) so launch #6 is adj_mma
    dummy_k<<<1, 32>>>();

    // convert adj to fp16
    convert_adj<<<NN * (NN / 4) / 256, blk>>>(adj);

    // input gconv: h = relu(adj @ (x@in_W) + x@in_Wl + in_b)
    proj_fused<<<gproj, blk, PROJ_SMEM>>>(x, IN_DIM, in_W, in_Wl, in_b, yth, U);
    adj_mma<<<gmma, blk, MMA_SMEM>>>(ahi, yth, U, nullptr, h, 1);

    for (int i = 0; i < LBLK; i++) {
        const float* W1  = blk_W1  + (size_t)i * HID * HID;
        const float* Wl1 = blk_Wl1 + (size_t)i * HID * HID;
        const float* b1  = blk_b1  + (size_t)i * HID;
        const float* W2  = blk_W2  + (size_t)i * HID * HID;
        const float* Wl2 = blk_Wl2 + (size_t)i * HID * HID;
        const float* b2  = blk_b2  + (size_t)i * HID;

        // t = relu(gconv(h))
        proj_fused<<<gproj, blk, PROJ_SMEM>>>(h, HID, W1, Wl1, b1, yth, U);
        adj_mma<<<gmma, blk, MMA_SMEM>>>(ahi, yth, U, nullptr, t, 1);

        // h = (h + relu(gconv(t))) * 0.5
        proj_fused<<<gproj, blk, PROJ_SMEM>>>(t, HID, W2, Wl2, b2, yth, U);
        adj_mma<<<gmma, blk, MMA_SMEM>>>(ahi, yth, U, h, h, 2);
    }

    // output head: x_out = adj @ (h@out_W) + h@out_Wl + out_b
    out_proj<<<NN / 256, blk>>>(h, out_W, out_Wl, out_b, Y3, U3);
    adj_small<<<512, blk>>>(adj, Y3, U3, out);

    // second output: h
    cudaMemcpyAsync(out + (size_t)NN * OUT_DIM, h,
                    (size_t)NN * HID * sizeof(float),
                    cudaMemcpyDeviceToDevice, 0);
}